// round 13
// baseline (speedup 1.0000x reference)
#include <cuda_runtime.h>
#include <cuda_bf16.h>
#include <math.h>
#include <stdint.h>

#define ROWB 528                 // bytes per row (256 bf16 = 512B + 16B pad)
#define LSIZE (128 * ROWB)       // 67584 bytes per weight image
#define ASIZE (64 * ROWB)        // 33792 bytes activation image (64 px)
#define NLAYERS 12
#define NT 128

__device__ __align__(16) unsigned char g_prep[NLAYERS * LSIZE];

// ---------------- helpers ---------------------------------------------------
__device__ __forceinline__ uint32_t smem_u32(const void* p) {
    uint32_t a;
    asm("{ .reg .u64 t; cvta.to.shared.u64 t, %1; cvt.u32.u64 %0, t; }" : "=r"(a) : "l"(p));
    return a;
}
__device__ __forceinline__ void ldsm4(uint32_t &r0, uint32_t &r1, uint32_t &r2,
                                      uint32_t &r3, uint32_t addr) {
    asm volatile("ldmatrix.sync.aligned.m8n8.x4.shared.b16 {%0,%1,%2,%3}, [%4];"
                 : "=r"(r0), "=r"(r1), "=r"(r2), "=r"(r3) : "r"(addr));
}
__device__ __forceinline__ void mma_bf16(float* d, uint32_t a0, uint32_t a1,
                                         uint32_t a2, uint32_t a3,
                                         uint32_t b0, uint32_t b1) {
    asm volatile(
        "mma.sync.aligned.m16n8k16.row.col.f32.bf16.bf16.f32 "
        "{%0,%1,%2,%3}, {%4,%5,%6,%7}, {%8,%9}, {%0,%1,%2,%3};"
        : "+f"(d[0]), "+f"(d[1]), "+f"(d[2]), "+f"(d[3])
        : "r"(a0), "r"(a1), "r"(a2), "r"(a3), "r"(b0), "r"(b1));
}
__device__ __forceinline__ void split_pair(float x, float y, uint32_t &hi, uint32_t &lo) {
    __nv_bfloat162 h = __floats2bfloat162_rn(x, y);
    float rx = __bfloat162float(__low2bfloat16(h));
    float ry = __bfloat162float(__high2bfloat16(h));
    __nv_bfloat162 l2 = __floats2bfloat162_rn(x - rx, y - ry);
    hi = *reinterpret_cast<uint32_t*>(&h);
    lo = *reinterpret_cast<uint32_t*>(&l2);
}

#define MBAR_INIT(mb, c) asm volatile("mbarrier.init.shared.b64 [%0], %1;" :: "r"(mb), "r"(c) : "memory")
#define MBAR_EXPECT_TX(mb, n) asm volatile("mbarrier.arrive.expect_tx.shared.b64 _, [%0], %1;" :: "r"(mb), "r"(n) : "memory")
#define BAR_SYNC(id, cnt) asm volatile("bar.sync %0, %1;" :: "r"(id), "r"(cnt) : "memory")

__device__ __forceinline__ void bulk_copy(uint32_t dst, const void* src,
                                          uint32_t bytes, uint32_t mbar) {
    asm volatile(
        "cp.async.bulk.shared::cta.global.mbarrier::complete_tx::bytes [%0], [%1], %2, [%3];"
        :: "r"(dst), "l"(src), "r"(bytes), "r"(mbar) : "memory");
}
__device__ __forceinline__ void mbar_wait(uint32_t mb, uint32_t parity) {
    uint32_t done;
    asm volatile(
        "{\n\t.reg .pred p;\n\t"
        "mbarrier.try_wait.parity.acquire.cta.shared::cta.b64 p, [%1], %2;\n\t"
        "selp.b32 %0, 1, 0, p;\n\t}"
        : "=r"(done) : "r"(mb), "r"(parity) : "memory");
    if (!done) {
        asm volatile(
            "{\n\t.reg .pred P1;\n\t"
            "W0_%=:\n\t"
            "mbarrier.try_wait.parity.acquire.cta.shared::cta.b64 P1, [%0], %1, 0x989680;\n\t"
            "@P1 bra.uni W1_%=;\n\t"
            "bra.uni W0_%=;\n\t"
            "W1_%=:\n\t}"
            :: "r"(mb), "r"(parity) : "memory");
    }
}

// ---------------- prep kernel: transpose + bf16-split weights ---------------
__global__ void prep_kernel(const float* __restrict__ vde_W,
                            const float* __restrict__ vh_W,
                            const float* __restrict__ hid_W,
                            const float* __restrict__ hW0,
                            const float* __restrict__ hW1)
{
    int l = blockIdx.x, kb = blockIdx.y, n = threadIdx.x;
    const float* W; int K;
    if (l == 0)      { W = vde_W; K = 32; }
    else if (l < 4)  { W = vh_W + (size_t)(l - 1) * 16384; K = 128; }
    else if (l < 10) { W = hid_W + (size_t)(l - 4) * 16384; K = 128; }
    else             { W = (l == 10) ? hW0 : hW1; K = 128; }
    if (kb * 16 >= K) return;
    __nv_bfloat16* row = (__nv_bfloat16*)(g_prep + (size_t)l * LSIZE + (size_t)n * ROWB);
    for (int k = kb * 16; k < kb * 16 + 16; k++) {
        float w = (l == 0 && k >= 18) ? 0.0f : W[(size_t)k * 128 + n];
        __nv_bfloat16 h = __float2bfloat16(w);
        __nv_bfloat16 lo = __float2bfloat16(w - __bfloat162float(h));
        row[k] = h;
        row[K + k] = lo;
    }
}

// ---------------- mma over one layer: warp tile 32m x 64n -------------------
// Per k-chunk: 12 ldsm.x4 (Ah2, Al2, Bh4, Bl4) feed 48 HMMA.
template<int K>
__device__ __forceinline__ void mma_layer(float (&acc)[2][8][4], uint32_t aU,
                                          uint32_t bU, int lane, int m0, int n0)
{
#pragma unroll
    for (int mt = 0; mt < 2; mt++)
#pragma unroll
        for (int nt = 0; nt < 8; nt++)
#pragma unroll
            for (int r = 0; r < 4; r++) acc[mt][nt][r] = 0.f;

    const int KS = K / 16;
    const uint32_t aBase = aU + (uint32_t)(m0 + (lane & 15)) * ROWB + ((lane >> 4) << 4);
    const uint32_t bBase = bU + (uint32_t)(n0 + (lane & 15)) * ROWB + ((lane >> 4) << 4);
#pragma unroll
    for (int kc = 0; kc < KS; kc++) {
        const int kHi = kc * 16;
        const int kLo = K + kc * 16;
        uint32_t ah[2][4], al[2][4], bh[4][4], bl[4][4];
#pragma unroll
        for (int mt = 0; mt < 2; mt++) {
            ldsm4(ah[mt][0], ah[mt][1], ah[mt][2], ah[mt][3],
                  aBase + (uint32_t)mt * 16 * ROWB + kHi * 2);
            ldsm4(al[mt][0], al[mt][1], al[mt][2], al[mt][3],
                  aBase + (uint32_t)mt * 16 * ROWB + kLo * 2);
        }
#pragma unroll
        for (int j = 0; j < 4; j++) {
            ldsm4(bh[j][0], bh[j][1], bh[j][2], bh[j][3],
                  bBase + (uint32_t)j * 16 * ROWB + kHi * 2);
            ldsm4(bl[j][0], bl[j][1], bl[j][2], bl[j][3],
                  bBase + (uint32_t)j * 16 * ROWB + kLo * 2);
        }
#pragma unroll
        for (int mt = 0; mt < 2; mt++)
#pragma unroll
            for (int j = 0; j < 4; j++)
#pragma unroll
                for (int jj = 0; jj < 2; jj++) {
                    float* d = acc[mt][2 * j + jj];
                    mma_bf16(d, ah[mt][0], ah[mt][1], ah[mt][2], ah[mt][3],
                             bh[j][jj], bh[j][jj + 2]);
                    mma_bf16(d, al[mt][0], al[mt][1], al[mt][2], al[mt][3],
                             bh[j][jj], bh[j][jj + 2]);
                    mma_bf16(d, ah[mt][0], ah[mt][1], ah[mt][2], ah[mt][3],
                             bl[j][jj], bl[j][jj + 2]);
                }
    }
}

// flags: 1=relu, 2=mulVH, 4=saveVH, 8=writeA, 16=head2
__device__ __forceinline__ void epilogue(
    int flags, float (&acc)[2][8][4], float (&vh)[2][8][4],
    const float* __restrict__ biasRow, const float* __restrict__ sW2,
    float* __restrict__ sOut, char* sA, int lane, int m0, int n0)
{
    const int cq = (lane & 3) * 2;
#pragma unroll
    for (int mt = 0; mt < 2; mt++) {
        const int r0 = m0 + mt * 16 + (lane >> 2), r1 = r0 + 8;
        float s0[4] = {0.f, 0.f, 0.f, 0.f}, s1[4] = {0.f, 0.f, 0.f, 0.f};
#pragma unroll
        for (int nt = 0; nt < 8; nt++) {
            const int n = n0 + nt * 8 + cq;
            float2 b = *(const float2*)(biasRow + n);
            float v0 = acc[mt][nt][0] + b.x, v1 = acc[mt][nt][1] + b.y;
            float v2 = acc[mt][nt][2] + b.x, v3 = acc[mt][nt][3] + b.y;
            if (flags & 1) {
                v0 = fmaxf(v0, 0.f); v1 = fmaxf(v1, 0.f);
                v2 = fmaxf(v2, 0.f); v3 = fmaxf(v3, 0.f);
            }
            if (flags & 2) {
                v0 *= vh[mt][nt][0]; v1 *= vh[mt][nt][1];
                v2 *= vh[mt][nt][2]; v3 *= vh[mt][nt][3];
            }
            if (flags & 4) {
                vh[mt][nt][0] = v0; vh[mt][nt][1] = v1;
                vh[mt][nt][2] = v2; vh[mt][nt][3] = v3;
            }
            if (flags & 8) {
                uint32_t h, l;
                split_pair(v0, v1, h, l);
                *(uint32_t*)(sA + (size_t)r0 * ROWB + n * 2)       = h;
                *(uint32_t*)(sA + (size_t)r0 * ROWB + 256 + n * 2) = l;
                split_pair(v2, v3, h, l);
                *(uint32_t*)(sA + (size_t)r1 * ROWB + n * 2)       = h;
                *(uint32_t*)(sA + (size_t)r1 * ROWB + 256 + n * 2) = l;
            }
            if (flags & 16) {
                float4 wa = *(const float4*)(sW2 + n * 4);
                float4 wb = *(const float4*)(sW2 + (n + 1) * 4);
                s0[0] += v0 * wa.x + v1 * wb.x; s0[1] += v0 * wa.y + v1 * wb.y;
                s0[2] += v0 * wa.z + v1 * wb.z; s0[3] += v0 * wa.w + v1 * wb.w;
                s1[0] += v2 * wa.x + v3 * wb.x; s1[1] += v2 * wa.y + v3 * wb.y;
                s1[2] += v2 * wa.z + v3 * wb.z; s1[3] += v2 * wa.w + v3 * wb.w;
            }
        }
        if (flags & 16) {
#pragma unroll
            for (int c = 0; c < 4; c++) {
                s0[c] += __shfl_xor_sync(0xffffffffu, s0[c], 1);
                s0[c] += __shfl_xor_sync(0xffffffffu, s0[c], 2);
                s1[c] += __shfl_xor_sync(0xffffffffu, s1[c], 1);
                s1[c] += __shfl_xor_sync(0xffffffffu, s1[c], 2);
            }
            if ((lane & 3) == 0) {
#pragma unroll
                for (int c = 0; c < 4; c++) {
                    atomicAdd(&sOut[r0 * 4 + c], s0[c]);
                    atomicAdd(&sOut[r1 * 4 + c], s1[c]);
                }
            }
        }
    }
}

// ------- main fused kernel: 64 px/CTA, 128 thr, 2 CTAs/SM, 2 groups/CTA -----
__global__ void __launch_bounds__(NT, 2) rc_mma_kernel(
    const int* __restrict__ vidx, const float* __restrict__ bary,
    const float* __restrict__ vdir, const float* __restrict__ emb,
    const float* __restrict__ vde_b, const float* __restrict__ vh_b,
    const float* __restrict__ hid_b, const float* __restrict__ hb0,
    const float* __restrict__ hb1,
    const float* __restrict__ hW2, const float* __restrict__ hb2,
    float* __restrict__ out, int n_pix)
{
    extern __shared__ char smem[];
    char*  sA    = smem;                                 // 64 x ROWB
    char*  sB    = smem + ASIZE;                         // 128 x ROWB
    float* sBias = (float*)(smem + ASIZE + LSIZE);       // 1536 f
    float* sW2   = sBias + 1536;                         // 528 f
    float* sScl  = sW2 + 528;                            // 192 f
    int*   sIdx  = (int*)(sScl + 192);                   // 192 i
    float* sOut  = (float*)(sIdx + 192);                 // 256 f
    int*   sCtr  = (int*)(sOut + 256);                   // 12 i

    const uint32_t aU = smem_u32(sA);
    const uint32_t bU = smem_u32(sB);
    const uint32_t mbar = smem_u32(sCtr + 12);

    const int tid  = threadIdx.x;
    const int lane = tid & 31;
    const int w    = tid >> 5;          // 0..3
    const int g    = tid >> 6;          // pixel group 0/1 (2 warps each)
    const int gbar = 1 + g;
    const int m0   = g * 32;
    const int n0   = (w & 1) * 64;
    const int base = blockIdx.x * 64;
    const bool gleader = (lane == 0) && ((w & 1) == 0);  // tid 0 and 64

    if (tid == 0) MBAR_INIT(mbar, 1);
    __syncthreads();
    if (tid == 0) {
        MBAR_EXPECT_TX(mbar, LSIZE);
        bulk_copy(bU, g_prep, LSIZE, mbar);
    }

    // ---- prologue ----
    for (int i = tid; i < 1536; i += NT) {
        int l = i >> 7, n = i & 127;
        const float* p;
        if (l == 0) p = vde_b;
        else if (l < 4) p = vh_b + (l - 1) * 128;
        else if (l < 10) p = hid_b + (l - 4) * 128;
        else p = (l == 10) ? hb0 : hb1;
        sBias[i] = p[n];
    }
    for (int i = tid; i < 512; i += NT) sW2[i] = hW2[i];
    if (tid < 4) sW2[512 + tid] = hb2[tid];
    sOut[tid] = 0.f; sOut[tid + 128] = 0.f;
    if (tid < 12) sCtr[tid] = 0;

    for (int job = tid; job < 192; job += NT) {
        int m = job & 63, j = job >> 6;
        int pix = base + m; if (pix >= n_pix) pix = n_pix - 1;
        int idx = vidx[pix * 3 + j] + 1;
        float bw = bary[pix * 3 + j];
        const float4* row = (const float4*)(emb + (size_t)idx * 128);
        float ss = 0.f;
#pragma unroll
        for (int i = 0; i < 32; i++) {
            float4 e = row[i];
            ss += e.x * e.x + e.y * e.y + e.z * e.z + e.w * e.w;
        }
        float nrm = sqrtf(ss);
        sScl[j * 64 + m] = bw * ((nrm > 1.0f) ? (1.0f / (nrm + 1e-7f)) : 1.0f);
        sIdx[j * 64 + m] = idx;
    }

    if (tid < 64) {
        int m = tid;
        int pix = base + m; if (pix >= n_pix) pix = n_pix - 1;
        float vd[3];
        vd[0] = vdir[pix * 3 + 0]; vd[1] = vdir[pix * 3 + 1]; vd[2] = vdir[pix * 3 + 2];
        float p[32];
#pragma unroll
        for (int i = 18; i < 32; i++) p[i] = 0.f;
        float sg[3];
#pragma unroll
        for (int j = 0; j < 3; j++)
            sg[j] = 6.283185307179586f / powf(0.9f, (float)(2 * j) / 6.0f);
#pragma unroll
        for (int i = 0; i < 3; i++)
#pragma unroll
            for (int j = 0; j < 3; j++) {
                float ph = vd[i] * sg[j];
                p[i * 6 + j]     = sinf(ph);
                p[i * 6 + j + 3] = cosf(ph);
            }
        uint32_t h[16], lo[16];
#pragma unroll
        for (int q = 0; q < 16; q++) split_pair(p[2 * q], p[2 * q + 1], h[q], lo[q]);
        char* rp = sA + (size_t)m * ROWB;
#pragma unroll
        for (int q = 0; q < 4; q++) {
            *(uint4*)(rp + q * 16)      = make_uint4(h[4*q], h[4*q+1], h[4*q+2], h[4*q+3]);
            *(uint4*)(rp + 64 + q * 16) = make_uint4(lo[4*q], lo[4*q+1], lo[4*q+2], lo[4*q+3]);
        }
    }
    __syncthreads();

    float acc[2][8][4];
    float vh[2][8][4];
    static const int LFLAGS[12] = {8, 9, 9, 5, 9, 9, 11, 9, 9, 9, 9, 17};

    for (int l = 0; l <= 11; l++) {
        mbar_wait(mbar, l & 1);
        BAR_SYNC(gbar, 64);             // group: prev epilogue A-writes done
        if (l == 0) mma_layer<32>(acc, aU, bU, lane, m0, n0);
        else        mma_layer<128>(acc, aU, bU, lane, m0, n0);
        BAR_SYNC(gbar, 64);             // group: all reads of A (and B) done

        if (l <= 10 && gleader) {
            int old = atomicAdd(&sCtr[l], 1);
            if (old == 1) {
                MBAR_EXPECT_TX(mbar, LSIZE);
                bulk_copy(bU, g_prep + (size_t)(l + 1) * LSIZE, LSIZE, mbar);
            }
        }

        if (l == 3) {
            // per-group embedding gather -> own 32 A rows (64 threads, 64 d ea)
            int t = tid & 63;
            int m = m0 + (t & 31), dc = t >> 5;      // dc 0..1, 64 d each
            int d0 = dc * 64;
            float4 a[16];
#pragma unroll
            for (int i = 0; i < 16; i++) a[i] = make_float4(0.f, 0.f, 0.f, 0.f);
#pragma unroll
            for (int j = 0; j < 3; j++) {
                int idx = sIdx[j * 64 + m];
                float sc = sScl[j * 64 + m];
                const float4* row = (const float4*)(emb + (size_t)idx * 128 + d0);
#pragma unroll
                for (int i = 0; i < 16; i++) {
                    float4 e = row[i];
                    a[i].x += sc * e.x; a[i].y += sc * e.y;
                    a[i].z += sc * e.z; a[i].w += sc * e.w;
                }
            }
            uint32_t h[32], lo[32];
#pragma unroll
            for (int i = 0; i < 16; i++) {
                split_pair(a[i].x, a[i].y, h[2*i],   lo[2*i]);
                split_pair(a[i].z, a[i].w, h[2*i+1], lo[2*i+1]);
            }
            char* rp = sA + (size_t)m * ROWB + dc * 128;
#pragma unroll
            for (int q = 0; q < 8; q++) {
                *(uint4*)(rp + q * 16)       = make_uint4(h[4*q], h[4*q+1], h[4*q+2], h[4*q+3]);
                *(uint4*)(rp + 256 + q * 16) = make_uint4(lo[4*q], lo[4*q+1], lo[4*q+2], lo[4*q+3]);
            }
        }

        epilogue(LFLAGS[l], acc, vh, sBias + l * 128, sW2, sOut, sA, lane, m0, n0);
    }

    // ---- final: write head2 result (per group) ----
    BAR_SYNC(gbar, 64);
    for (int t = tid & 63; t < 128; t += 64) {
        int m = m0 + (t >> 2), c = t & 3;
        int pix = base + m;
        if (pix < n_pix)
            out[(size_t)pix * 4 + c] = sOut[m * 4 + c] + sW2[512 + c];
    }
}

// ---------------- launch -----------------------------------------------------
extern "C" void kernel_launch(void* const* d_in, const int* in_sizes, int n_in,
                              void* d_out, int out_size)
{
    const int*   vidx  = (const int*)  d_in[0];
    const float* bary  = (const float*)d_in[1];
    const float* vdir  = (const float*)d_in[2];
    const float* emb   = (const float*)d_in[3];
    const float* vde_W = (const float*)d_in[4];
    const float* vde_b = (const float*)d_in[5];
    const float* vh_W  = (const float*)d_in[6];
    const float* vh_b  = (const float*)d_in[7];
    const float* hid_W = (const float*)d_in[8];
    const float* hid_b = (const float*)d_in[9];
    const float* hW0   = (const float*)d_in[10];
    const float* hb0   = (const float*)d_in[11];
    const float* hW1   = (const float*)d_in[12];
    const float* hb1   = (const float*)d_in[13];
    const float* hW2   = (const float*)d_in[14];
    const float* hb2   = (const float*)d_in[15];
    float* out = (float*)d_out;

    int n_pix = in_sizes[0] / 3;
    int grid  = (n_pix + 63) / 64;

    dim3 pgrid(NLAYERS, 8);
    prep_kernel<<<pgrid, 128>>>(vde_W, vh_W, hid_W, hW0, hW1);

    const int SMEM_BYTES = ASIZE + LSIZE + (1536 + 528 + 192 + 192 + 256 + 12) * 4 + 16;
    cudaFuncSetAttribute(rc_mma_kernel,
                         cudaFuncAttributeMaxDynamicSharedMemorySize, SMEM_BYTES);
    cudaFuncSetAttribute(rc_mma_kernel,
                         cudaFuncAttributePreferredSharedMemoryCarveout, 100);

    rc_mma_kernel<<<grid, NT, SMEM_BYTES>>>(
        vidx, bary, vdir, emb, vde_b, vh_b, hid_b, hb0, hb1,
        hW2, hb2, out, n_pix);
}

// round 14
// speedup vs baseline: 1.0325x; 1.0325x over previous
#include <cuda_runtime.h>
#include <cuda_bf16.h>
#include <math.h>
#include <stdint.h>

#define ROWB 528                 // bytes per row (256 bf16 = 512B + 16B pad)
#define LSIZE (128 * ROWB)       // 67584 bytes per weight image
#define HLF   (64 * ROWB)        // 33792 half image (n rows 0-63 / 64-127)
#define ASIZE (64 * ROWB)        // 33792 activation image (64 px)
#define NLAYERS 12
#define NT 256

__device__ __align__(16) unsigned char g_prep[NLAYERS * LSIZE];

// ---------------- helpers ---------------------------------------------------
__device__ __forceinline__ uint32_t smem_u32(const void* p) {
    uint32_t a;
    asm("{ .reg .u64 t; cvta.to.shared.u64 t, %1; cvt.u32.u64 %0, t; }" : "=r"(a) : "l"(p));
    return a;
}
__device__ __forceinline__ void ldsm4(uint32_t &r0, uint32_t &r1, uint32_t &r2,
                                      uint32_t &r3, uint32_t addr) {
    asm volatile("ldmatrix.sync.aligned.m8n8.x4.shared.b16 {%0,%1,%2,%3}, [%4];"
                 : "=r"(r0), "=r"(r1), "=r"(r2), "=r"(r3) : "r"(addr));
}
__device__ __forceinline__ void mma_bf16(float* d, uint32_t a0, uint32_t a1,
                                         uint32_t a2, uint32_t a3,
                                         uint32_t b0, uint32_t b1) {
    asm volatile(
        "mma.sync.aligned.m16n8k16.row.col.f32.bf16.bf16.f32 "
        "{%0,%1,%2,%3}, {%4,%5,%6,%7}, {%8,%9}, {%0,%1,%2,%3};"
        : "+f"(d[0]), "+f"(d[1]), "+f"(d[2]), "+f"(d[3])
        : "r"(a0), "r"(a1), "r"(a2), "r"(a3), "r"(b0), "r"(b1));
}
__device__ __forceinline__ void split_pair(float x, float y, uint32_t &hi, uint32_t &lo) {
    __nv_bfloat162 h = __floats2bfloat162_rn(x, y);
    float rx = __bfloat162float(__low2bfloat16(h));
    float ry = __bfloat162float(__high2bfloat16(h));
    __nv_bfloat162 l2 = __floats2bfloat162_rn(x - rx, y - ry);
    hi = *reinterpret_cast<uint32_t*>(&h);
    lo = *reinterpret_cast<uint32_t*>(&l2);
}

#define MBAR_INIT(mb, c) asm volatile("mbarrier.init.shared.b64 [%0], %1;" :: "r"(mb), "r"(c) : "memory")
#define MBAR_EXPECT_TX(mb, n) asm volatile("mbarrier.arrive.expect_tx.shared.b64 _, [%0], %1;" :: "r"(mb), "r"(n) : "memory")
#define BAR_SYNC(id, cnt) asm volatile("bar.sync %0, %1;" :: "r"(id), "r"(cnt) : "memory")

__device__ __forceinline__ void bulk_copy(uint32_t dst, const void* src,
                                          uint32_t bytes, uint32_t mbar) {
    asm volatile(
        "cp.async.bulk.shared::cta.global.mbarrier::complete_tx::bytes [%0], [%1], %2, [%3];"
        :: "r"(dst), "l"(src), "r"(bytes), "r"(mbar) : "memory");
}
__device__ __forceinline__ void mbar_wait(uint32_t mb, uint32_t parity) {
    uint32_t done;
    asm volatile(
        "{\n\t.reg .pred p;\n\t"
        "mbarrier.try_wait.parity.acquire.cta.shared::cta.b64 p, [%1], %2;\n\t"
        "selp.b32 %0, 1, 0, p;\n\t}"
        : "=r"(done) : "r"(mb), "r"(parity) : "memory");
    if (!done) {
        asm volatile(
            "{\n\t.reg .pred P1;\n\t"
            "W0_%=:\n\t"
            "mbarrier.try_wait.parity.acquire.cta.shared::cta.b64 P1, [%0], %1, 0x989680;\n\t"
            "@P1 bra.uni W1_%=;\n\t"
            "bra.uni W0_%=;\n\t"
            "W1_%=:\n\t}"
            :: "r"(mb), "r"(parity) : "memory");
    }
}

// ---------------- prep kernel: transpose + bf16-split weights ---------------
__global__ void prep_kernel(const float* __restrict__ vde_W,
                            const float* __restrict__ vh_W,
                            const float* __restrict__ hid_W,
                            const float* __restrict__ hW0,
                            const float* __restrict__ hW1)
{
    int l = blockIdx.x, kb = blockIdx.y, n = threadIdx.x;
    const float* W; int K;
    if (l == 0)      { W = vde_W; K = 32; }
    else if (l < 4)  { W = vh_W + (size_t)(l - 1) * 16384; K = 128; }
    else if (l < 10) { W = hid_W + (size_t)(l - 4) * 16384; K = 128; }
    else             { W = (l == 10) ? hW0 : hW1; K = 128; }
    if (kb * 16 >= K) return;
    __nv_bfloat16* row = (__nv_bfloat16*)(g_prep + (size_t)l * LSIZE + (size_t)n * ROWB);
    for (int k = kb * 16; k < kb * 16 + 16; k++) {
        float w = (l == 0 && k >= 18) ? 0.0f : W[(size_t)k * 128 + n];
        __nv_bfloat16 h = __float2bfloat16(w);
        __nv_bfloat16 lo = __float2bfloat16(w - __bfloat162float(h));
        row[k] = h;
        row[K + k] = lo;
    }
}

// ---------------- mma over one layer: warp tile 32m x 32n -------------------
template<int K>
__device__ __forceinline__ void mma_layer(float (&acc)[2][4][4], uint32_t aU,
                                          uint32_t bU, int lane, int m0, int n0)
{
#pragma unroll
    for (int mt = 0; mt < 2; mt++)
#pragma unroll
        for (int nt = 0; nt < 4; nt++)
#pragma unroll
            for (int r = 0; r < 4; r++) acc[mt][nt][r] = 0.f;

    const int KS = K / 16;
    const uint32_t aBase = aU + (uint32_t)(m0 + (lane & 15)) * ROWB + ((lane >> 4) << 4);
    const uint32_t bBase = bU + (uint32_t)(n0 + (lane & 15)) * ROWB + ((lane >> 4) << 4);
#pragma unroll
    for (int kc = 0; kc < KS; kc++) {
        const int kHi = kc * 16;
        const int kLo = K + kc * 16;
        uint32_t ah[2][4], al[2][4], bh[2][4], bl[2][4];
        ldsm4(ah[0][0], ah[0][1], ah[0][2], ah[0][3], aBase + kHi * 2);
        ldsm4(ah[1][0], ah[1][1], ah[1][2], ah[1][3], aBase + 16 * ROWB + kHi * 2);
        ldsm4(bh[0][0], bh[0][1], bh[0][2], bh[0][3], bBase + kHi * 2);
        ldsm4(bh[1][0], bh[1][1], bh[1][2], bh[1][3], bBase + 16 * ROWB + kHi * 2);
        ldsm4(al[0][0], al[0][1], al[0][2], al[0][3], aBase + kLo * 2);
        ldsm4(al[1][0], al[1][1], al[1][2], al[1][3], aBase + 16 * ROWB + kLo * 2);
        ldsm4(bl[0][0], bl[0][1], bl[0][2], bl[0][3], bBase + kLo * 2);
        ldsm4(bl[1][0], bl[1][1], bl[1][2], bl[1][3], bBase + 16 * ROWB + kLo * 2);
#pragma unroll
        for (int mt = 0; mt < 2; mt++)
#pragma unroll
            for (int bt = 0; bt < 2; bt++) {
                mma_bf16(acc[mt][bt * 2],     ah[mt][0], ah[mt][1], ah[mt][2], ah[mt][3],
                         bh[bt][0], bh[bt][2]);
                mma_bf16(acc[mt][bt * 2 + 1], ah[mt][0], ah[mt][1], ah[mt][2], ah[mt][3],
                         bh[bt][1], bh[bt][3]);
                mma_bf16(acc[mt][bt * 2],     al[mt][0], al[mt][1], al[mt][2], al[mt][3],
                         bh[bt][0], bh[bt][2]);
                mma_bf16(acc[mt][bt * 2 + 1], al[mt][0], al[mt][1], al[mt][2], al[mt][3],
                         bh[bt][1], bh[bt][3]);
                mma_bf16(acc[mt][bt * 2],     ah[mt][0], ah[mt][1], ah[mt][2], ah[mt][3],
                         bl[bt][0], bl[bt][2]);
                mma_bf16(acc[mt][bt * 2 + 1], ah[mt][0], ah[mt][1], ah[mt][2], ah[mt][3],
                         bl[bt][1], bl[bt][3]);
            }
    }
}

// flags: 1=relu, 2=mulVH, 4=saveVH, 8=writeA, 16=head2
__device__ __forceinline__ void epilogue(
    int flags, float (&acc)[2][4][4], float (&vh)[2][4][4],
    const float* __restrict__ biasRow, const float* __restrict__ sW2,
    float* __restrict__ sOut, char* sA, int lane, int m0, int n0)
{
    const int cq = (lane & 3) * 2;
    float s[2][2][4];
    if (flags & 16) {
#pragma unroll
        for (int mt = 0; mt < 2; mt++)
#pragma unroll
            for (int h = 0; h < 2; h++)
#pragma unroll
                for (int c = 0; c < 4; c++) s[mt][h][c] = 0.f;
    }
#pragma unroll
    for (int mt = 0; mt < 2; mt++) {
        const int r0 = m0 + mt * 16 + (lane >> 2), r1 = r0 + 8;
#pragma unroll
        for (int nt = 0; nt < 4; nt++) {
            const int n = n0 + nt * 8 + cq;
            float2 b = *(const float2*)(biasRow + n);
            float v0 = acc[mt][nt][0] + b.x, v1 = acc[mt][nt][1] + b.y;
            float v2 = acc[mt][nt][2] + b.x, v3 = acc[mt][nt][3] + b.y;
            if (flags & 1) {
                v0 = fmaxf(v0, 0.f); v1 = fmaxf(v1, 0.f);
                v2 = fmaxf(v2, 0.f); v3 = fmaxf(v3, 0.f);
            }
            if (flags & 2) {
                v0 *= vh[mt][nt][0]; v1 *= vh[mt][nt][1];
                v2 *= vh[mt][nt][2]; v3 *= vh[mt][nt][3];
            }
            if (flags & 4) {
                vh[mt][nt][0] = v0; vh[mt][nt][1] = v1;
                vh[mt][nt][2] = v2; vh[mt][nt][3] = v3;
            }
            if (flags & 8) {
                uint32_t h, l;
                split_pair(v0, v1, h, l);
                *(uint32_t*)(sA + (size_t)r0 * ROWB + n * 2)       = h;
                *(uint32_t*)(sA + (size_t)r0 * ROWB + 256 + n * 2) = l;
                split_pair(v2, v3, h, l);
                *(uint32_t*)(sA + (size_t)r1 * ROWB + n * 2)       = h;
                *(uint32_t*)(sA + (size_t)r1 * ROWB + 256 + n * 2) = l;
            }
            if (flags & 16) {
                float4 wa = *(const float4*)(sW2 + n * 4);
                float4 wb = *(const float4*)(sW2 + (n + 1) * 4);
                s[mt][0][0] += v0 * wa.x + v1 * wb.x; s[mt][0][1] += v0 * wa.y + v1 * wb.y;
                s[mt][0][2] += v0 * wa.z + v1 * wb.z; s[mt][0][3] += v0 * wa.w + v1 * wb.w;
                s[mt][1][0] += v2 * wa.x + v3 * wb.x; s[mt][1][1] += v2 * wa.y + v3 * wb.y;
                s[mt][1][2] += v2 * wa.z + v3 * wb.z; s[mt][1][3] += v2 * wa.w + v3 * wb.w;
            }
        }
    }
    if (flags & 16) {
#pragma unroll
        for (int mt = 0; mt < 2; mt++)
#pragma unroll
            for (int h = 0; h < 2; h++)
#pragma unroll
                for (int c = 0; c < 4; c++) {
                    s[mt][h][c] += __shfl_xor_sync(0xffffffffu, s[mt][h][c], 1);
                    s[mt][h][c] += __shfl_xor_sync(0xffffffffu, s[mt][h][c], 2);
                }
        if ((lane & 3) == 0) {
#pragma unroll
            for (int mt = 0; mt < 2; mt++) {
                const int r0 = m0 + mt * 16 + (lane >> 2);
#pragma unroll
                for (int c = 0; c < 4; c++) {
                    atomicAdd(&sOut[r0 * 4 + c],       s[mt][0][c]);
                    atomicAdd(&sOut[(r0 + 8) * 4 + c], s[mt][1][c]);
                }
            }
        }
    }
}

// -------- main: 64 px/CTA, 2 CTAs/SM, 2 groups, half-split pipelined B ------
__global__ void __launch_bounds__(NT, 2) rc_mma_kernel(
    const int* __restrict__ vidx, const float* __restrict__ bary,
    const float* __restrict__ vdir, const float* __restrict__ emb,
    const float* __restrict__ vde_b, const float* __restrict__ vh_b,
    const float* __restrict__ hid_b, const float* __restrict__ hb0,
    const float* __restrict__ hb1,
    const float* __restrict__ hW2, const float* __restrict__ hb2,
    float* __restrict__ out, int n_pix)
{
    extern __shared__ char smem[];
    char*  sA    = smem;                                 // 64 x ROWB
    char*  sB    = smem + ASIZE;                         // 128 x ROWB
    float* sBias = (float*)(smem + ASIZE + LSIZE);       // 1536 f
    float* sW2   = sBias + 1536;                         // 528 f
    float* sScl  = sW2 + 528;                            // 192 f
    int*   sIdx  = (int*)(sScl + 192);                   // 192 i
    float* sOut  = (float*)(sIdx + 192);                 // 256 f
    int*   sCtrH = (int*)(sOut + 256);                   // 24 i (12 layers x 2)

    const uint32_t aU = smem_u32(sA);
    const uint32_t bU = smem_u32(sB);
    const uint32_t mb0 = smem_u32(sCtrH + 24);           // 8-aligned
    const uint32_t mb1 = mb0 + 8;

    const int tid  = threadIdx.x;
    const int lane = tid & 31;
    const int w    = tid >> 5;
    const int g    = tid >> 7;          // pixel group 0/1
    const int gbar = 1 + g;
    const int m0   = g * 32;
    const int n0   = (w & 3) * 32;
    const int hf   = (w & 3) >> 1;      // B half: n0<64 -> 0, else 1
    const uint32_t mbh = hf ? mb1 : mb0;
    const int base = blockIdx.x * 64;

    if (tid == 0) { MBAR_INIT(mb0, 1); MBAR_INIT(mb1, 1); }
    __syncthreads();
    if (tid == 0) {
        MBAR_EXPECT_TX(mb0, HLF);
        bulk_copy(bU, g_prep, HLF, mb0);
        MBAR_EXPECT_TX(mb1, HLF);
        bulk_copy(bU + HLF, g_prep + HLF, HLF, mb1);
    }

    // ---- prologue ----
    for (int i = tid; i < 1536; i += NT) {
        int l = i >> 7, n = i & 127;
        const float* p;
        if (l == 0) p = vde_b;
        else if (l < 4) p = vh_b + (l - 1) * 128;
        else if (l < 10) p = hid_b + (l - 4) * 128;
        else p = (l == 10) ? hb0 : hb1;
        sBias[i] = p[n];
    }
    for (int i = tid; i < 512; i += NT) sW2[i] = hW2[i];
    if (tid < 4) sW2[512 + tid] = hb2[tid];
    sOut[tid] = 0.f;
    if (tid < 24) sCtrH[tid] = 0;

    if (tid < 192) {
        int m = tid & 63, j = tid >> 6;
        int pix = base + m; if (pix >= n_pix) pix = n_pix - 1;
        int idx = vidx[pix * 3 + j] + 1;
        float bw = bary[pix * 3 + j];
        const float4* row = (const float4*)(emb + (size_t)idx * 128);
        float ss = 0.f;
#pragma unroll
        for (int i = 0; i < 32; i++) {
            float4 e = row[i];
            ss += e.x * e.x + e.y * e.y + e.z * e.z + e.w * e.w;
        }
        float nrm = sqrtf(ss);
        sScl[j * 64 + m] = bw * ((nrm > 1.0f) ? (1.0f / (nrm + 1e-7f)) : 1.0f);
        sIdx[j * 64 + m] = idx;
    }

    if (tid < 64) {
        int m = tid;
        int pix = base + m; if (pix >= n_pix) pix = n_pix - 1;
        float vd[3];
        vd[0] = vdir[pix * 3 + 0]; vd[1] = vdir[pix * 3 + 1]; vd[2] = vdir[pix * 3 + 2];
        float p[32];
#pragma unroll
        for (int i = 18; i < 32; i++) p[i] = 0.f;
        float sg[3];
#pragma unroll
        for (int j = 0; j < 3; j++)
            sg[j] = 6.283185307179586f / powf(0.9f, (float)(2 * j) / 6.0f);
#pragma unroll
        for (int i = 0; i < 3; i++)
#pragma unroll
            for (int j = 0; j < 3; j++) {
                float ph = vd[i] * sg[j];
                p[i * 6 + j]     = sinf(ph);
                p[i * 6 + j + 3] = cosf(ph);
            }
        uint32_t h[16], lo[16];
#pragma unroll
        for (int q = 0; q < 16; q++) split_pair(p[2 * q], p[2 * q + 1], h[q], lo[q]);
        char* rp = sA + (size_t)m * ROWB;
#pragma unroll
        for (int q = 0; q < 4; q++) {
            *(uint4*)(rp + q * 16)      = make_uint4(h[4*q], h[4*q+1], h[4*q+2], h[4*q+3]);
            *(uint4*)(rp + 64 + q * 16) = make_uint4(lo[4*q], lo[4*q+1], lo[4*q+2], lo[4*q+3]);
        }
    }
    __syncthreads();

    float acc[2][4][4];
    float vh[2][4][4];
    static const int LFLAGS[12] = {8, 9, 9, 5, 9, 9, 11, 9, 9, 9, 9, 17};

    for (int l = 0; l <= 11; l++) {
        mbar_wait(mbh, l & 1);          // wait only this warp's B half
        BAR_SYNC(gbar, 128);            // group: prev epilogue A-writes done
        if (l == 0) mma_layer<32>(acc, aU, bU, lane, m0, n0);
        else        mma_layer<128>(acc, aU, bU, lane, m0, n0);

        // B half dead for this warp; 4th warp (both groups) triggers refill.
        // LDSM data is consumed before the HMMAs that precede this atomic.
        if (l <= 10 && lane == 0) {
            int old = atomicAdd(&sCtrH[l * 2 + hf], 1);
            if (old == 3) {
                MBAR_EXPECT_TX(mbh, HLF);
                bulk_copy(bU + (uint32_t)hf * HLF,
                          g_prep + (size_t)(l + 1) * LSIZE + (size_t)hf * HLF,
                          HLF, mbh);
            }
        }
        BAR_SYNC(gbar, 128);            // group: all A reads done

        if (l == 3) {
            // per-group embedding gather -> own A rows (before epilogue)
            int t = tid & 127;
            int m = m0 + (t & 31), dc = t >> 5;      // dc 0..3, 32 d each
            int d0 = dc * 32;
            float4 a[8];
#pragma unroll
            for (int i = 0; i < 8; i++) a[i] = make_float4(0.f, 0.f, 0.f, 0.f);
#pragma unroll
            for (int j = 0; j < 3; j++) {
                int idx = sIdx[j * 64 + m];
                float sc = sScl[j * 64 + m];
                const float4* row = (const float4*)(emb + (size_t)idx * 128 + d0);
#pragma unroll
                for (int i = 0; i < 8; i++) {
                    float4 e = row[i];
                    a[i].x += sc * e.x; a[i].y += sc * e.y;
                    a[i].z += sc * e.z; a[i].w += sc * e.w;
                }
            }
            uint32_t h[16], lo[16];
#pragma unroll
            for (int i = 0; i < 8; i++) {
                split_pair(a[i].x, a[i].y, h[2*i],   lo[2*i]);
                split_pair(a[i].z, a[i].w, h[2*i+1], lo[2*i+1]);
            }
            char* rp = sA + (size_t)m * ROWB + dc * 64;
#pragma unroll
            for (int q = 0; q < 4; q++) {
                *(uint4*)(rp + q * 16)       = make_uint4(h[4*q], h[4*q+1], h[4*q+2], h[4*q+3]);
                *(uint4*)(rp + 256 + q * 16) = make_uint4(lo[4*q], lo[4*q+1], lo[4*q+2], lo[4*q+3]);
            }
        }

        epilogue(LFLAGS[l], acc, vh, sBias + l * 128, sW2, sOut, sA, lane, m0, n0);
    }

    // ---- final: write head2 result (per group) ----
    BAR_SYNC(gbar, 128);
    {
        int t = tid & 127;
        int m = m0 + (t >> 2), c = t & 3;
        int pix = base + m;
        if (pix < n_pix)
            out[(size_t)pix * 4 + c] = sOut[m * 4 + c] + sW2[512 + c];
    }
}

// ---------------- launch -----------------------------------------------------
extern "C" void kernel_launch(void* const* d_in, const int* in_sizes, int n_in,
                              void* d_out, int out_size)
{
    const int*   vidx  = (const int*)  d_in[0];
    const float* bary  = (const float*)d_in[1];
    const float* vdir  = (const float*)d_in[2];
    const float* emb   = (const float*)d_in[3];
    const float* vde_W = (const float*)d_in[4];
    const float* vde_b = (const float*)d_in[5];
    const float* vh_W  = (const float*)d_in[6];
    const float* vh_b  = (const float*)d_in[7];
    const float* hid_W = (const float*)d_in[8];
    const float* hid_b = (const float*)d_in[9];
    const float* hW0   = (const float*)d_in[10];
    const float* hb0   = (const float*)d_in[11];
    const float* hW1   = (const float*)d_in[12];
    const float* hb1   = (const float*)d_in[13];
    const float* hW2   = (const float*)d_in[14];
    const float* hb2   = (const float*)d_in[15];
    float* out = (float*)d_out;

    int n_pix = in_sizes[0] / 3;
    int grid  = (n_pix + 63) / 64;

    dim3 pgrid(NLAYERS, 8);
    prep_kernel<<<pgrid, 128>>>(vde_W, vh_W, hid_W, hW0, hW1);

    const int SMEM_BYTES = ASIZE + LSIZE + (1536 + 528 + 192 + 192 + 256 + 24) * 4 + 16;
    cudaFuncSetAttribute(rc_mma_kernel,
                         cudaFuncAttributeMaxDynamicSharedMemorySize, SMEM_BYTES);
    cudaFuncSetAttribute(rc_mma_kernel,
                         cudaFuncAttributePreferredSharedMemoryCarveout, 100);

    rc_mma_kernel<<<grid, NT, SMEM_BYTES>>>(
        vidx, bary, vdir, emb, vde_b, vh_b, hid_b, hb0, hb1,
        hW2, hb2, out, n_pix);
}

// round 15
// speedup vs baseline: 1.1163x; 1.0811x over previous
#include <cuda_runtime.h>
#include <cuda_bf16.h>
#include <math.h>
#include <stdint.h>

#define ROWB 528                 // bytes per row (256 bf16 = 512B + 16B pad)
#define LSIZE (128 * ROWB)       // 67584 bytes per weight image
#define ASIZE (64 * ROWB)        // 33792 bytes activation image (64 px)
#define NLAYERS 12
#define NT 256
#define NV1 100001

__device__ __align__(16) unsigned char g_prep[NLAYERS * LSIZE];
__device__ float g_scale[NV1];

// ---------------- helpers ---------------------------------------------------
__device__ __forceinline__ uint32_t smem_u32(const void* p) {
    uint32_t a;
    asm("{ .reg .u64 t; cvta.to.shared.u64 t, %1; cvt.u32.u64 %0, t; }" : "=r"(a) : "l"(p));
    return a;
}
__device__ __forceinline__ void ldsm4(uint32_t &r0, uint32_t &r1, uint32_t &r2,
                                      uint32_t &r3, uint32_t addr) {
    asm volatile("ldmatrix.sync.aligned.m8n8.x4.shared.b16 {%0,%1,%2,%3}, [%4];"
                 : "=r"(r0), "=r"(r1), "=r"(r2), "=r"(r3) : "r"(addr));
}
__device__ __forceinline__ void mma_bf16(float* d, uint32_t a0, uint32_t a1,
                                         uint32_t a2, uint32_t a3,
                                         uint32_t b0, uint32_t b1) {
    asm volatile(
        "mma.sync.aligned.m16n8k16.row.col.f32.bf16.bf16.f32 "
        "{%0,%1,%2,%3}, {%4,%5,%6,%7}, {%8,%9}, {%0,%1,%2,%3};"
        : "+f"(d[0]), "+f"(d[1]), "+f"(d[2]), "+f"(d[3])
        : "r"(a0), "r"(a1), "r"(a2), "r"(a3), "r"(b0), "r"(b1));
}
__device__ __forceinline__ void split_pair(float x, float y, uint32_t &hi, uint32_t &lo) {
    __nv_bfloat162 h = __floats2bfloat162_rn(x, y);
    float rx = __bfloat162float(__low2bfloat16(h));
    float ry = __bfloat162float(__high2bfloat16(h));
    __nv_bfloat162 l2 = __floats2bfloat162_rn(x - rx, y - ry);
    hi = *reinterpret_cast<uint32_t*>(&h);
    lo = *reinterpret_cast<uint32_t*>(&l2);
}

#define MBAR_INIT(mb, c) asm volatile("mbarrier.init.shared.b64 [%0], %1;" :: "r"(mb), "r"(c) : "memory")
#define MBAR_EXPECT_TX(mb, n) asm volatile("mbarrier.arrive.expect_tx.shared.b64 _, [%0], %1;" :: "r"(mb), "r"(n) : "memory")
#define BAR_SYNC(id, cnt) asm volatile("bar.sync %0, %1;" :: "r"(id), "r"(cnt) : "memory")

__device__ __forceinline__ void bulk_copy(uint32_t dst, const void* src,
                                          uint32_t bytes, uint32_t mbar) {
    asm volatile(
        "cp.async.bulk.shared::cta.global.mbarrier::complete_tx::bytes [%0], [%1], %2, [%3];"
        :: "r"(dst), "l"(src), "r"(bytes), "r"(mbar) : "memory");
}
__device__ __forceinline__ void mbar_wait(uint32_t mb, uint32_t parity) {
    uint32_t done;
    asm volatile(
        "{\n\t.reg .pred p;\n\t"
        "mbarrier.try_wait.parity.acquire.cta.shared::cta.b64 p, [%1], %2;\n\t"
        "selp.b32 %0, 1, 0, p;\n\t}"
        : "=r"(done) : "r"(mb), "r"(parity) : "memory");
    if (!done) {
        asm volatile(
            "{\n\t.reg .pred P1;\n\t"
            "W0_%=:\n\t"
            "mbarrier.try_wait.parity.acquire.cta.shared::cta.b64 P1, [%0], %1, 0x989680;\n\t"
            "@P1 bra.uni W1_%=;\n\t"
            "bra.uni W0_%=;\n\t"
            "W1_%=:\n\t}"
            :: "r"(mb), "r"(parity) : "memory");
    }
}

// ---------------- norm kernel: per-row renorm scale (warp per row) ----------
__global__ void norm_kernel(const float* __restrict__ emb)
{
    int row = blockIdx.x * 4 + (threadIdx.x >> 5);
    if (row >= NV1) return;
    int lane = threadIdx.x & 31;
    float4 e = *(const float4*)(emb + (size_t)row * 128 + lane * 4);
    float ss = e.x * e.x + e.y * e.y + e.z * e.z + e.w * e.w;
#pragma unroll
    for (int o = 16; o > 0; o >>= 1)
        ss += __shfl_xor_sync(0xffffffffu, ss, o);
    if (lane == 0) {
        float nrm = sqrtf(ss);
        g_scale[row] = (nrm > 1.0f) ? (1.0f / (nrm + 1e-7f)) : 1.0f;
    }
}

// ---------------- prep kernel: transpose + bf16-split weights ---------------
__global__ void prep_kernel(const float* __restrict__ vde_W,
                            const float* __restrict__ vh_W,
                            const float* __restrict__ hid_W,
                            const float* __restrict__ hW0,
                            const float* __restrict__ hW1)
{
    int l = blockIdx.x, kb = blockIdx.y, n = threadIdx.x;
    const float* W; int K;
    if (l == 0)      { W = vde_W; K = 32; }
    else if (l < 4)  { W = vh_W + (size_t)(l - 1) * 16384; K = 128; }
    else if (l < 10) { W = hid_W + (size_t)(l - 4) * 16384; K = 128; }
    else             { W = (l == 10) ? hW0 : hW1; K = 128; }
    if (kb * 16 >= K) return;
    __nv_bfloat16* row = (__nv_bfloat16*)(g_prep + (size_t)l * LSIZE + (size_t)n * ROWB);
    for (int k = kb * 16; k < kb * 16 + 16; k++) {
        float w = (l == 0 && k >= 18) ? 0.0f : W[(size_t)k * 128 + n];
        __nv_bfloat16 h = __float2bfloat16(w);
        __nv_bfloat16 lo = __float2bfloat16(w - __bfloat162float(h));
        row[k] = h;
        row[K + k] = lo;
    }
}

// ---------------- mma over one layer: warp tile 32m x 32n -------------------
template<int K>
__device__ __forceinline__ void mma_layer(float (&acc)[2][4][4], uint32_t aU,
                                          uint32_t bU, int lane, int m0, int n0)
{
#pragma unroll
    for (int mt = 0; mt < 2; mt++)
#pragma unroll
        for (int nt = 0; nt < 4; nt++)
#pragma unroll
            for (int r = 0; r < 4; r++) acc[mt][nt][r] = 0.f;

    const int KS = K / 16;
    const uint32_t aBase = aU + (uint32_t)(m0 + (lane & 15)) * ROWB + ((lane >> 4) << 4);
    const uint32_t bBase = bU + (uint32_t)(n0 + (lane & 15)) * ROWB + ((lane >> 4) << 4);
#pragma unroll
    for (int kc = 0; kc < KS; kc++) {
        const int kHi = kc * 16;
        const int kLo = K + kc * 16;
        uint32_t ah[2][4], al[2][4], bh[2][4], bl[2][4];
        ldsm4(ah[0][0], ah[0][1], ah[0][2], ah[0][3], aBase + kHi * 2);
        ldsm4(ah[1][0], ah[1][1], ah[1][2], ah[1][3], aBase + 16 * ROWB + kHi * 2);
        ldsm4(bh[0][0], bh[0][1], bh[0][2], bh[0][3], bBase + kHi * 2);
        ldsm4(bh[1][0], bh[1][1], bh[1][2], bh[1][3], bBase + 16 * ROWB + kHi * 2);
        ldsm4(al[0][0], al[0][1], al[0][2], al[0][3], aBase + kLo * 2);
        ldsm4(al[1][0], al[1][1], al[1][2], al[1][3], aBase + 16 * ROWB + kLo * 2);
        ldsm4(bl[0][0], bl[0][1], bl[0][2], bl[0][3], bBase + kLo * 2);
        ldsm4(bl[1][0], bl[1][1], bl[1][2], bl[1][3], bBase + 16 * ROWB + kLo * 2);
#pragma unroll
        for (int mt = 0; mt < 2; mt++)
#pragma unroll
            for (int bt = 0; bt < 2; bt++) {
                mma_bf16(acc[mt][bt * 2],     ah[mt][0], ah[mt][1], ah[mt][2], ah[mt][3],
                         bh[bt][0], bh[bt][2]);
                mma_bf16(acc[mt][bt * 2 + 1], ah[mt][0], ah[mt][1], ah[mt][2], ah[mt][3],
                         bh[bt][1], bh[bt][3]);
                mma_bf16(acc[mt][bt * 2],     al[mt][0], al[mt][1], al[mt][2], al[mt][3],
                         bh[bt][0], bh[bt][2]);
                mma_bf16(acc[mt][bt * 2 + 1], al[mt][0], al[mt][1], al[mt][2], al[mt][3],
                         bh[bt][1], bh[bt][3]);
                mma_bf16(acc[mt][bt * 2],     ah[mt][0], ah[mt][1], ah[mt][2], ah[mt][3],
                         bl[bt][0], bl[bt][2]);
                mma_bf16(acc[mt][bt * 2 + 1], ah[mt][0], ah[mt][1], ah[mt][2], ah[mt][3],
                         bl[bt][1], bl[bt][3]);
            }
    }
}

// flags: 1=relu, 2=mulVH, 4=saveVH, 8=writeA, 16=head2
__device__ __forceinline__ void epilogue(
    int flags, float (&acc)[2][4][4], float (&vh)[2][4][4],
    const float* __restrict__ biasRow, const float* __restrict__ sW2,
    float* __restrict__ sOut, char* sA, int lane, int m0, int n0)
{
    const int cq = (lane & 3) * 2;
    float s[2][2][4];
    if (flags & 16) {
#pragma unroll
        for (int mt = 0; mt < 2; mt++)
#pragma unroll
            for (int h = 0; h < 2; h++)
#pragma unroll
                for (int c = 0; c < 4; c++) s[mt][h][c] = 0.f;
    }
#pragma unroll
    for (int mt = 0; mt < 2; mt++) {
        const int r0 = m0 + mt * 16 + (lane >> 2), r1 = r0 + 8;
#pragma unroll
        for (int nt = 0; nt < 4; nt++) {
            const int n = n0 + nt * 8 + cq;
            float2 b = *(const float2*)(biasRow + n);
            float v0 = acc[mt][nt][0] + b.x, v1 = acc[mt][nt][1] + b.y;
            float v2 = acc[mt][nt][2] + b.x, v3 = acc[mt][nt][3] + b.y;
            if (flags & 1) {
                v0 = fmaxf(v0, 0.f); v1 = fmaxf(v1, 0.f);
                v2 = fmaxf(v2, 0.f); v3 = fmaxf(v3, 0.f);
            }
            if (flags & 2) {
                v0 *= vh[mt][nt][0]; v1 *= vh[mt][nt][1];
                v2 *= vh[mt][nt][2]; v3 *= vh[mt][nt][3];
            }
            if (flags & 4) {
                vh[mt][nt][0] = v0; vh[mt][nt][1] = v1;
                vh[mt][nt][2] = v2; vh[mt][nt][3] = v3;
            }
            if (flags & 8) {
                uint32_t h, l;
                split_pair(v0, v1, h, l);
                *(uint32_t*)(sA + (size_t)r0 * ROWB + n * 2)       = h;
                *(uint32_t*)(sA + (size_t)r0 * ROWB + 256 + n * 2) = l;
                split_pair(v2, v3, h, l);
                *(uint32_t*)(sA + (size_t)r1 * ROWB + n * 2)       = h;
                *(uint32_t*)(sA + (size_t)r1 * ROWB + 256 + n * 2) = l;
            }
            if (flags & 16) {
                float4 wa = *(const float4*)(sW2 + n * 4);
                float4 wb = *(const float4*)(sW2 + (n + 1) * 4);
                s[mt][0][0] += v0 * wa.x + v1 * wb.x; s[mt][0][1] += v0 * wa.y + v1 * wb.y;
                s[mt][0][2] += v0 * wa.z + v1 * wb.z; s[mt][0][3] += v0 * wa.w + v1 * wb.w;
                s[mt][1][0] += v2 * wa.x + v3 * wb.x; s[mt][1][1] += v2 * wa.y + v3 * wb.y;
                s[mt][1][2] += v2 * wa.z + v3 * wb.z; s[mt][1][3] += v2 * wa.w + v3 * wb.w;
            }
        }
    }
    if (flags & 16) {
#pragma unroll
        for (int mt = 0; mt < 2; mt++)
#pragma unroll
            for (int h = 0; h < 2; h++)
#pragma unroll
                for (int c = 0; c < 4; c++) {
                    s[mt][h][c] += __shfl_xor_sync(0xffffffffu, s[mt][h][c], 1);
                    s[mt][h][c] += __shfl_xor_sync(0xffffffffu, s[mt][h][c], 2);
                }
        if ((lane & 3) == 0) {
#pragma unroll
            for (int mt = 0; mt < 2; mt++) {
                const int r0 = m0 + mt * 16 + (lane >> 2);
#pragma unroll
                for (int c = 0; c < 4; c++) {
                    atomicAdd(&sOut[r0 * 4 + c],       s[mt][0][c]);
                    atomicAdd(&sOut[(r0 + 8) * 4 + c], s[mt][1][c]);
                }
            }
        }
    }
}

// ---------------- main fused kernel: 64 px/CTA, 2 CTAs/SM, 2 groups/CTA -----
__global__ void __launch_bounds__(NT, 2) rc_mma_kernel(
    const int* __restrict__ vidx, const float* __restrict__ bary,
    const float* __restrict__ vdir, const float* __restrict__ emb,
    const float* __restrict__ vde_b, const float* __restrict__ vh_b,
    const float* __restrict__ hid_b, const float* __restrict__ hb0,
    const float* __restrict__ hb1,
    const float* __restrict__ hW2, const float* __restrict__ hb2,
    float* __restrict__ out, int n_pix)
{
    extern __shared__ char smem[];
    char*  sA    = smem;                                 // 64 x ROWB
    char*  sB    = smem + ASIZE;                         // 128 x ROWB
    float* sBias = (float*)(smem + ASIZE + LSIZE);       // 1536 f
    float* sW2   = sBias + 1536;                         // 528 f
    float* sScl  = sW2 + 528;                            // 192 f
    int*   sIdx  = (int*)(sScl + 192);                   // 192 i
    float* sOut  = (float*)(sIdx + 192);                 // 256 f
    int*   sCtr  = (int*)(sOut + 256);                   // 12 i

    const uint32_t aU = smem_u32(sA);
    const uint32_t bU = smem_u32(sB);
    const uint32_t mbar = smem_u32(sCtr + 12);

    const int tid  = threadIdx.x;
    const int lane = tid & 31;
    const int w    = tid >> 5;
    const int g    = tid >> 7;          // pixel group 0/1
    const int gbar = 1 + g;
    const int m0   = g * 32;
    const int n0   = (w & 3) * 32;
    const int base = blockIdx.x * 64;
    const bool gleader = (lane == 0) && ((w & 3) == 0);  // tid 0 and 128

    if (tid == 0) MBAR_INIT(mbar, 1);
    __syncthreads();
    if (tid == 0) {
        MBAR_EXPECT_TX(mbar, LSIZE);
        bulk_copy(bU, g_prep, LSIZE, mbar);
    }

    // ---- prologue ----
    for (int i = tid; i < 1536; i += NT) {
        int l = i >> 7, n = i & 127;
        const float* p;
        if (l == 0) p = vde_b;
        else if (l < 4) p = vh_b + (l - 1) * 128;
        else if (l < 10) p = hid_b + (l - 4) * 128;
        else p = (l == 10) ? hb0 : hb1;
        sBias[i] = p[n];
    }
    for (int i = tid; i < 512; i += NT) sW2[i] = hW2[i];
    if (tid < 4) sW2[512 + tid] = hb2[tid];
    sOut[tid] = 0.f;
    if (tid < 12) sCtr[tid] = 0;

    // renorm scales from precomputed table (1 scalar LDG per vertex)
    if (tid < 192) {
        int m = tid & 63, j = tid >> 6;
        int pix = base + m; if (pix >= n_pix) pix = n_pix - 1;
        int idx = vidx[pix * 3 + j] + 1;
        float bw = bary[pix * 3 + j];
        sScl[j * 64 + m] = bw * g_scale[idx];
        sIdx[j * 64 + m] = idx;
    }

    if (tid < 64) {
        int m = tid;
        int pix = base + m; if (pix >= n_pix) pix = n_pix - 1;
        float vd[3];
        vd[0] = vdir[pix * 3 + 0]; vd[1] = vdir[pix * 3 + 1]; vd[2] = vdir[pix * 3 + 2];
        float p[32];
#pragma unroll
        for (int i = 18; i < 32; i++) p[i] = 0.f;
        float sg[3];
#pragma unroll
        for (int j = 0; j < 3; j++)
            sg[j] = 6.283185307179586f / powf(0.9f, (float)(2 * j) / 6.0f);
#pragma unroll
        for (int i = 0; i < 3; i++)
#pragma unroll
            for (int j = 0; j < 3; j++) {
                float ph = vd[i] * sg[j];
                p[i * 6 + j]     = sinf(ph);
                p[i * 6 + j + 3] = cosf(ph);
            }
        uint32_t h[16], lo[16];
#pragma unroll
        for (int q = 0; q < 16; q++) split_pair(p[2 * q], p[2 * q + 1], h[q], lo[q]);
        char* rp = sA + (size_t)m * ROWB;
#pragma unroll
        for (int q = 0; q < 4; q++) {
            *(uint4*)(rp + q * 16)      = make_uint4(h[4*q], h[4*q+1], h[4*q+2], h[4*q+3]);
            *(uint4*)(rp + 64 + q * 16) = make_uint4(lo[4*q], lo[4*q+1], lo[4*q+2], lo[4*q+3]);
        }
    }
    __syncthreads();

    float acc[2][4][4];
    float vh[2][4][4];
    static const int LFLAGS[12] = {8, 9, 9, 5, 9, 9, 11, 9, 9, 9, 9, 17};

    for (int l = 0; l <= 11; l++) {
        mbar_wait(mbar, l & 1);
        BAR_SYNC(gbar, 128);            // group: prev epilogue A-writes done
        if (l == 0) mma_layer<32>(acc, aU, bU, lane, m0, n0);
        else        mma_layer<128>(acc, aU, bU, lane, m0, n0);
        BAR_SYNC(gbar, 128);            // group: all reads of A (and B) done

        if (l <= 10 && gleader) {
            int old = atomicAdd(&sCtr[l], 1);
            if (old == 1) {
                MBAR_EXPECT_TX(mbar, LSIZE);
                bulk_copy(bU, g_prep + (size_t)(l + 1) * LSIZE, LSIZE, mbar);
            }
        }

        if (l == 3) {
            // per-group embedding gather -> own A rows (before epilogue)
            int t = tid & 127;
            int m = m0 + (t & 31), dc = t >> 5;      // dc 0..3, 32 d each
            int d0 = dc * 32;
            float4 a[8];
#pragma unroll
            for (int i = 0; i < 8; i++) a[i] = make_float4(0.f, 0.f, 0.f, 0.f);
#pragma unroll
            for (int j = 0; j < 3; j++) {
                int idx = sIdx[j * 64 + m];
                float sc = sScl[j * 64 + m];
                const float4* row = (const float4*)(emb + (size_t)idx * 128 + d0);
#pragma unroll
                for (int i = 0; i < 8; i++) {
                    float4 e = row[i];
                    a[i].x += sc * e.x; a[i].y += sc * e.y;
                    a[i].z += sc * e.z; a[i].w += sc * e.w;
                }
            }
            uint32_t h[16], lo[16];
#pragma unroll
            for (int i = 0; i < 8; i++) {
                split_pair(a[i].x, a[i].y, h[2*i],   lo[2*i]);
                split_pair(a[i].z, a[i].w, h[2*i+1], lo[2*i+1]);
            }
            char* rp = sA + (size_t)m * ROWB + dc * 64;
#pragma unroll
            for (int q = 0; q < 4; q++) {
                *(uint4*)(rp + q * 16)       = make_uint4(h[4*q], h[4*q+1], h[4*q+2], h[4*q+3]);
                *(uint4*)(rp + 256 + q * 16) = make_uint4(lo[4*q], lo[4*q+1], lo[4*q+2], lo[4*q+3]);
            }
        }

        epilogue(LFLAGS[l], acc, vh, sBias + l * 128, sW2, sOut, sA, lane, m0, n0);
    }

    // ---- final: write head2 result (per group) ----
    BAR_SYNC(gbar, 128);
    {
        int t = tid & 127;
        int m = m0 + (t >> 2), c = t & 3;
        int pix = base + m;
        if (pix < n_pix)
            out[(size_t)pix * 4 + c] = sOut[m * 4 + c] + sW2[512 + c];
    }
}

// ---------------- launch -----------------------------------------------------
extern "C" void kernel_launch(void* const* d_in, const int* in_sizes, int n_in,
                              void* d_out, int out_size)
{
    const int*   vidx  = (const int*)  d_in[0];
    const float* bary  = (const float*)d_in[1];
    const float* vdir  = (const float*)d_in[2];
    const float* emb   = (const float*)d_in[3];
    const float* vde_W = (const float*)d_in[4];
    const float* vde_b = (const float*)d_in[5];
    const float* vh_W  = (const float*)d_in[6];
    const float* vh_b  = (const float*)d_in[7];
    const float* hid_W = (const float*)d_in[8];
    const float* hid_b = (const float*)d_in[9];
    const float* hW0   = (const float*)d_in[10];
    const float* hb0   = (const float*)d_in[11];
    const float* hW1   = (const float*)d_in[12];
    const float* hb1   = (const float*)d_in[13];
    const float* hW2   = (const float*)d_in[14];
    const float* hb2   = (const float*)d_in[15];
    float* out = (float*)d_out;

    int n_pix = in_sizes[0] / 3;
    int grid  = (n_pix + 63) / 64;

    dim3 pgrid(NLAYERS, 8);
    prep_kernel<<<pgrid, 128>>>(vde_W, vh_W, hid_W, hW0, hW1);
    norm_kernel<<<(NV1 + 3) / 4, 128>>>(emb);

    const int SMEM_BYTES = ASIZE + LSIZE + (1536 + 528 + 192 + 192 + 256 + 12) * 4 + 16;
    cudaFuncSetAttribute(rc_mma_kernel,
                         cudaFuncAttributeMaxDynamicSharedMemorySize, SMEM_BYTES);
    cudaFuncSetAttribute(rc_mma_kernel,
                         cudaFuncAttributePreferredSharedMemoryCarveout, 100);

    rc_mma_kernel<<<grid, NT, SMEM_BYTES>>>(
        vidx, bary, vdir, emb, vde_b, vh_b, hid_b, hb0, hb1,
        hW2, hb2, out, n_pix);
}